// round 11
// baseline (speedup 1.0000x reference)
#include <cuda_runtime.h>
#include <cuda_fp16.h>
#include <cstdint>

// GeometryOptimalTransport: sparse Sinkhorn attention. b=4, n=4096, d=64.
// R11: all 16 Sinkhorn half-passes fused into ONE persistent kernel
//      (128 co-resident blocks, per-batch software barriers); setup kernels
//      merged. 5 graph nodes total (was 21). Linear-domain lists from R10.

#define BB 4
#define NN 4096
#define DD 64
#define STRIDE 640            // max valid neighbors ~515+6sigma; multiple of 128
#define WPB 8
#define THREADS 256
#define NSLAB 16
#define NXBIN 16
#define NCELL2 16             // 16x16 target cells for the epilogue
#define TCAP2 64              // targets per cell cap (mean 16)
#define PBLK 32               // blocks per batch in the fused pass kernel
#define SENTINEL 0u           // K = 0, off = 0 -> contributes exactly 0

// log2(e) / (EPS + 1e-8), EPS = 0.01
__device__ __constant__ float C2 = (float)(1.4426950408889634 / 0.01000001);

__device__ uint32_t g_listT[BB * NN * STRIDE];   // entries: (f16 K)<<16 | idx<<2
__device__ uint32_t g_listS[BB * NN * STRIDE];
__device__ int g_cntT[BB * NN];                  // padded counts (multiple of 128)
__device__ int g_cntS[BB * NN];
__device__ float g_eu[BB * NN];                  // 2^u
__device__ float g_ev[BB * NN];                  // 2^v
__device__ __half2 g_Vh[BB * NN * (DD / 2)];     // V in half2 (2MB)
// (yslab, xbin) sorted candidate arrays
__device__ float2 g_sortloc[2][BB][NN];
__device__ unsigned short g_sortid[2][BB][NN];
__device__ float2 g_loc2[2][BB][NN];
__device__ unsigned short g_id2[2][BB][NN];
__device__ int g_binstart[2][BB][NSLAB * NXBIN + 1];
// target cell lists for the epilogue
__device__ int g_tcnt[BB * NCELL2 * NCELL2];
__device__ int g_tlist[BB * NCELL2 * NCELL2][TCAP2];
// software barrier state (g_arrive returns to 0 after each barrier;
// g_phase grows monotonically across graph replays — sense-reversing)
__device__ int g_arrive[BB];
__device__ int g_phase[BB];

static __device__ __forceinline__ float ex2f(float x) {
    float y; asm("ex2.approx.ftz.f32 %0, %1;" : "=f"(y) : "f"(x)); return y;
}
static __device__ __forceinline__ float rcpf(float x) {
    float y; asm("rcp.approx.ftz.f32 %0, %1;" : "=f"(y) : "f"(x)); return y;
}
// gather float at byte offset (entry low 16 bits hold idx*4)
static __device__ __forceinline__ float gat(const float* s, uint32_t e) {
    return *reinterpret_cast<const float*>(
        reinterpret_cast<const char*>(s) + (e & 0xFFFCu));
}
static __device__ __forceinline__ float kof(uint32_t e) {   // f16 K -> f32
    return __half2float(__ushort_as_half((unsigned short)(e >> 16)));
}

// ---------------------------------------------------------------------------
// Merged stage 1+2: y-slab counting sort, then per-slab x-bin sort, in one
// block per (b, mode). Deterministic (ballot compaction). Also zeroes g_tcnt.
// ---------------------------------------------------------------------------
__global__ void slab_xbin(const float2* __restrict__ tlocs,
                          const float2* __restrict__ slocs)
{
    const int b = blockIdx.x, mode = blockIdx.y;
    const float2* cl = (mode ? tlocs : slocs) + (size_t)b * NN;
    __shared__ int s_cnt[NSLAB + 1];
    const int tid = threadIdx.x, wid = tid >> 5, lane = tid & 31;  // 16 warps

    if (blockIdx.x == 0 && blockIdx.y == 0)
        for (int k = tid; k < BB * NCELL2 * NCELL2; k += 512) g_tcnt[k] = 0;

    // --- phase 1: y-slab sort (warp w handles slab w) ---
    int c = 0;
    for (int i0 = 0; i0 < NN; i0 += 32) {
        const float2 p = cl[i0 + lane];
        const int sl = min(max((int)(p.y * (float)NSLAB), 0), NSLAB - 1);
        c += __popc(__ballot_sync(0xffffffffu, sl == wid));
    }
    if (lane == 0) s_cnt[wid + 1] = c;
    __syncthreads();
    if (tid == 0) {
        s_cnt[0] = 0;
        for (int k = 1; k <= NSLAB; k++) s_cnt[k] += s_cnt[k - 1];
    }
    __syncthreads();
    {
        int base = s_cnt[wid];
        for (int i0 = 0; i0 < NN; i0 += 32) {
            const float2 p = cl[i0 + lane];
            const int sl = min(max((int)(p.y * (float)NSLAB), 0), NSLAB - 1);
            const bool m = (sl == wid);
            const unsigned bal = __ballot_sync(0xffffffffu, m);
            if (m) {
                const int o = base + __popc(bal & ((1u << lane) - 1u));
                g_sortloc[mode][b][o] = p;
                g_sortid[mode][b][o] = (unsigned short)(i0 + lane);
            }
            base += __popc(bal);
        }
    }
    __syncthreads();   // g_sortloc/g_sortid visible block-wide

    // --- phase 2: x-bin sort within slab (warp w = slab w) ---
    const int beg = s_cnt[wid];
    const int end = s_cnt[wid + 1];
    int base = beg;
    for (int xb = 0; xb < NXBIN; xb++) {
        if (lane == 0) g_binstart[mode][b][wid * NXBIN + xb] = base;
        for (int i0 = beg; i0 < end; i0 += 32) {
            const int i = i0 + lane;
            bool m = false;
            float2 p; unsigned short id = 0;
            if (i < end) {
                p = g_sortloc[mode][b][i];
                id = g_sortid[mode][b][i];
                const int xbin = min(max((int)(p.x * (float)NXBIN), 0), NXBIN - 1);
                m = (xbin == xb);
            }
            const unsigned bal = __ballot_sync(0xffffffffu, m);
            if (m) {
                const int o = base + __popc(bal & ((1u << lane) - 1u));
                g_loc2[mode][b][o] = p;
                g_id2[mode][b][o] = id;
            }
            base += __popc(bal);
        }
    }
    if (wid == NSLAB - 1 && lane == 0)
        g_binstart[mode][b][NSLAB * NXBIN] = end;
}

// ---------------------------------------------------------------------------
// Merged: V (f32)->half2 convert + target cell binning.
// ---------------------------------------------------------------------------
__global__ void bin_convert(const float2* __restrict__ feats2,
                            const float2* __restrict__ tlocs)
{
    const int i = blockIdx.x * THREADS + threadIdx.x;   // over BB*NN*32
    const float2 v = feats2[i];
    g_Vh[i] = __floats2half2_rn(v.x, v.y);
    if (i < BB * NN) {
        const int b = i >> 12;
        const int t = i & (NN - 1);
        const float2 p = tlocs[i];
        const int cx = min(max((int)(p.x * (float)NCELL2), 0), NCELL2 - 1);
        const int cy = min(max((int)(p.y * (float)NCELL2), 0), NCELL2 - 1);
        const int cell = b * NCELL2 * NCELL2 + cy * NCELL2 + cx;
        const int pos = atomicAdd(&g_tcnt[cell], 1);
        if (pos < TCAP2) g_tlist[cell][pos] = t;
    }
}

// ---------------------------------------------------------------------------
// Build compacted pair lists; candidates limited to the (yslab,xbin) window.
// Entries: (f16 K)<<16 | idx<<2, K = exp(-dsq/eps). SENTINEL padding to a
// multiple of 128. mode 1 also inits ev = 1.
// ---------------------------------------------------------------------------
__global__ void build_lists(const float2* __restrict__ tlocs,
                            const float2* __restrict__ slocs)
{
    __shared__ float2 s_loc[NN];
    __shared__ unsigned short s_id[NN];
    __shared__ int s_bs[NSLAB * NXBIN + 1];       // 257 entries
    const int mode = blockIdx.z;
    const float2* row_locs = (mode ? slocs : tlocs);
    const int b = blockIdx.y;
    const int tid = threadIdx.x;
    #pragma unroll
    for (int k = 0; k < NN / THREADS; k++) {
        s_loc[tid + k * THREADS] = g_loc2[mode][b][tid + k * THREADS];
        s_id[tid + k * THREADS]  = g_id2[mode][b][tid + k * THREADS];
    }
    s_bs[tid] = g_binstart[mode][b][tid];
    if (tid == 0)
        s_bs[NSLAB * NXBIN] = g_binstart[mode][b][NSLAB * NXBIN];
    __syncthreads();

    const int wid = tid >> 5, lane = tid & 31;
    const int r = blockIdx.x * WPB + wid;
    const int g = b * NN + r;
    const float2 rl = row_locs[(size_t)b * NN + r];
    uint32_t* lp = (mode ? g_listS : g_listT) + (size_t)g * STRIDE;

    const int lo  = max((int)((rl.y - 0.2001f) * (float)NSLAB), 0);
    const int hi  = min((int)((rl.y + 0.2001f) * (float)NSLAB), NSLAB - 1);
    const int xlo = max((int)((rl.x - 0.2001f) * (float)NXBIN), 0);
    const int xhi = min((int)((rl.x + 0.2001f) * (float)NXBIN), NXBIN - 1);

    int n = 0;
    for (int s = lo; s <= hi; s++) {
        const int beg = s_bs[s * NXBIN + xlo];
        const int end = s_bs[s * NXBIN + xhi + 1];
        for (int i0 = beg; i0 < end; i0 += 32) {
            const int i = i0 + lane;
            bool pred = false;
            float dsq = 0.0f;
            unsigned short sid = 0;
            if (i < end) {
                const float2 c = s_loc[i];
                const float dx = rl.x - c.x;
                const float dy = rl.y - c.y;
                // match reference rounding: mul, mul, add (no fma contraction)
                dsq = __fadd_rn(__fmul_rn(dx, dx), __fmul_rn(dy, dy));
                pred = dsq < 0.04f;
                sid = s_id[i];
            }
            const unsigned bal = __ballot_sync(0xffffffffu, pred);
            if (pred) {
                const float K = ex2f(dsq * (-C2));   // exp(-dsq/eps)
                const unsigned short h = __half_as_ushort(__float2half(K));
                const uint32_t e = ((uint32_t)sid << 2) | ((uint32_t)h << 16);
                const int ofs = n + __popc(bal & ((1u << lane) - 1u));
                if (ofs < STRIDE) lp[ofs] = e;
            }
            n += __popc(bal);
        }
    }
    n = min(n, STRIDE);
    const int npad = min((n + 127) & ~127, STRIDE);
    for (int i = n + lane; i < npad; i += 32) lp[i] = SENTINEL;
    if (lane == 0) {
        (mode ? g_cntS : g_cntT)[g] = npad;
        if (mode) g_ev[g] = 1.0f;
    }
}

// ---------------------------------------------------------------------------
// Per-batch software barrier across PBLK co-resident blocks.
// Sense-reversing via monotone phase counter; arrive counter self-resets.
// ---------------------------------------------------------------------------
static __device__ __forceinline__ void batch_barrier(int b)
{
    __syncthreads();
    if (threadIdx.x == 0) {
        __threadfence();                       // publish this block's writes
        volatile int* ph = &g_phase[b];
        const int old = *ph;
        if (atomicAdd(&g_arrive[b], 1) == PBLK - 1) {
            g_arrive[b] = 0;
            __threadfence();
            *ph = old + 1;                     // release
        } else {
            int backoff = 32;
            while (*ph == old) {
                __nanosleep(backoff);
                if (backoff < 1024) backoff <<= 1;
            }
        }
        __threadfence();                       // acquire
    }
    __syncthreads();
}

// ---------------------------------------------------------------------------
// ALL 16 Sinkhorn half-iterations in one persistent kernel.
// Grid (PBLK, BB) x 1024 threads: 128 blocks, all co-resident (<=148 SMs,
// <=64 regs, 16KB smem). Each block handles 128 rows (4 per warp) of its
// batch per half-pass; per-batch barrier between half-passes. The 4 batch
// chains run concurrently and hide each other's barrier stalls.
//   dir 0: eu[t] = 1 / sum_s K * ev[s]
//   dir 1: ev[s] = 1 / sum_t K * eu[t]
// ---------------------------------------------------------------------------
static __device__ __forceinline__ float chunk_sum(uint4 q, const float* s_in) {
    float a;
    a  = kof(q.x) * gat(s_in, q.x);
    a  = fmaf(kof(q.y), gat(s_in, q.y), a);
    a  = fmaf(kof(q.z), gat(s_in, q.z), a);
    a  = fmaf(kof(q.w), gat(s_in, q.w), a);
    return a;
}

__global__ void __launch_bounds__(1024, 1) sinkhorn_all()
{
    __shared__ float s_in[NN];
    const int b = blockIdx.y;
    const int blk = blockIdx.x;                    // 0..PBLK-1
    const int tid = threadIdx.x, wid = tid >> 5, lane = tid & 31;
    const int rbase = blk * (NN / PBLK) + wid;     // rows rbase + k*32, k<4

    #pragma unroll 1
    for (int half = 0; half < 16; half++) {
        const int dir = half & 1;
        const float* vin = dir ? g_eu : g_ev;
        reinterpret_cast<float4*>(s_in)[tid] =
            reinterpret_cast<const float4*>(vin + b * NN)[tid];
        __syncthreads();

        const int* cnt = dir ? g_cntS : g_cntT;
        const uint32_t* lbase = dir ? g_listS : g_listT;
        float* vout = dir ? g_ev : g_eu;

        #pragma unroll 1
        for (int rr = 0; rr < NN / PBLK / 32; rr++) {          // 4 rows/warp
            const int g = b * NN + rbase + rr * 32;
            const int n = cnt[g];                              // <= 640
            const uint4* lp = reinterpret_cast<const uint4*>(
                lbase + (size_t)g * STRIDE);
            const int nc = n >> 7;                             // 0..5 chunks

            uint4 q0, q1, q2, q3, q4;
            if (nc > 0) q0 = lp[lane];
            if (nc > 1) q1 = lp[32 + lane];
            if (nc > 2) q2 = lp[64 + lane];
            if (nc > 3) q3 = lp[96 + lane];
            if (nc > 4) q4 = lp[128 + lane];

            float acc = 0.0f;
            if (nc > 0) acc += chunk_sum(q0, s_in);
            if (nc > 1) acc += chunk_sum(q1, s_in);
            if (nc > 2) acc += chunk_sum(q2, s_in);
            if (nc > 3) acc += chunk_sum(q3, s_in);
            if (nc > 4) acc += chunk_sum(q4, s_in);

            #pragma unroll
            for (int o = 16; o; o >>= 1)
                acc += __shfl_xor_sync(0xffffffffu, acc, o);
            if (lane == 0) vout[g] = rcpf(acc);
        }
        batch_barrier(b);          // also separates s_in reuse across halves
    }
}

// ---------------------------------------------------------------------------
// Epilogue: one CTA per (cell, batch); one warp per target of the cell.
// w = K * ev[s] * eu[t]. smem (w, off) broadcast + half2 V FMAs.
// ---------------------------------------------------------------------------
__global__ void __launch_bounds__(512)
final_kernel(float* __restrict__ out)
{
    __shared__ float s_v[NN];                  // ev for this batch
    __shared__ float2 s_w[16][32];             // (w, off-as-float) per warp
    const int b = blockIdx.y;
    const int cell = blockIdx.x;               // 0..255
    const int tid = threadIdx.x, wid = tid >> 5, lane = tid & 31;  // 16 warps

    #pragma unroll
    for (int k = 0; k < NN / 512; k++)
        s_v[tid + k * 512] = g_ev[b * NN + tid + k * 512];
    __syncthreads();

    const int gcell = b * NCELL2 * NCELL2 + cell;
    const int tcnt = min(g_tcnt[gcell], TCAP2);
    const __half2* Vb = g_Vh + (size_t)b * NN * (DD / 2);

    for (int ti = wid; ti < tcnt; ti += 16) {
        const int t = g_tlist[gcell][ti];
        const int g = b * NN + t;
        const int n = g_cntT[g];               // multiple of 128 (or 0)
        const uint32_t* lp = g_listT + (size_t)g * STRIDE;
        const float eut = g_eu[g];

        float2 acc = make_float2(0.0f, 0.0f);
        uint32_t e = (n > 0) ? lp[lane] : SENTINEL;
        for (int i0 = 0; i0 < n; i0 += 32) {
            const float w = kof(e) * gat(s_v, e) * eut;
            s_w[wid][lane] = make_float2(w, __uint_as_float(e & 0xFFFCu));
            __syncwarp();
            if (i0 + 32 < n) e = lp[i0 + 32 + lane];   // prefetch next chunk
            #pragma unroll 8
            for (int j = 0; j < 32; j++) {
                const float2 p = s_w[wid][j];
                if (p.x != 0.0f) {   // warp-uniform; skips padding/underflow
                    const float2 vv = __half22float2(
                        Vb[((size_t)__float_as_uint(p.y) << 3) + lane]);
                    acc.x = fmaf(p.x, vv.x, acc.x);
                    acc.y = fmaf(p.x, vv.y, acc.y);
                }
            }
            __syncwarp();
        }
        reinterpret_cast<float2*>(out)[(size_t)g * (DD / 2) + lane] = acc;
    }
}

// ---------------------------------------------------------------------------
extern "C" void kernel_launch(void* const* d_in, const int* in_sizes, int n_in,
                              void* d_out, int out_size)
{
    const float* feats  = (const float*)d_in[0];        // (b, src, 64) f32
    const float2* slocs = (const float2*)d_in[1];       // (b, src, 2)  f32
    const float2* tlocs = (const float2*)d_in[2];       // (b, tgt, 2)  f32
    float* out = (float*)d_out;                          // (b, tgt, 64) f32

    slab_xbin<<<dim3(BB, 2), 512>>>(tlocs, slocs);
    bin_convert<<<BB * NN * (DD / 2) / THREADS, THREADS>>>(
        (const float2*)feats, tlocs);
    build_lists<<<dim3(NN / WPB, BB, 2), THREADS>>>(tlocs, slocs);
    sinkhorn_all<<<dim3(PBLK, BB), 1024>>>();
    final_kernel<<<dim3(NCELL2 * NCELL2, BB), 512>>>(out);
}